// round 13
// baseline (speedup 1.0000x reference)
#include <cuda_runtime.h>
#include <cuda_fp16.h>
#include <math.h>
#include <stdint.h>

// Problem constants
#define B_ 2
#define S_ 1024
#define D_ 1024
#define H_ 16
#define DK_ 64
#define DFF_ 4096
#define L_ 4
#define V_ 50257
#define M_TOK (B_ * S_)   // 2048 rows
#define QKV3 (3 * D_)     // 3072

// ---------------- scratch (static device globals; no allocation allowed) ----
__device__ float  g_x[M_TOK * D_];        // residual stream (fp32)
__device__ __half g_xh[M_TOK * D_];       // fp16 copy of x (QKV A input)
__device__ __half g_qkv[M_TOK * QKV3];    // fused q|k|v (fp16)
__device__ __half g_y[M_TOK * D_];        // attention out (fp16)
__device__ __half g_t[M_TOK * D_];        // ln out (fp16)
__device__ __half g_h[M_TOK * DFF_];      // mlp hidden (fp16)

// transposed fp16 weights: per layer [wqT][wkT][wvT][woT][w1T][w2T]
#define LAYER_WELEMS (4 * D_ * D_ + D_ * DFF_ + DFF_ * D_)
__device__ __half g_wH[(size_t)L_ * LAYER_WELEMS];
__device__ float  g_bqkv[L_ * QKV3];       // packed qkv bias (fp32)
__device__ __half g_teH[(size_t)V_ * D_];  // fp16 token embedding ([V,D]=[N,K])

// ---------------- PTX helpers (sm_80+ portable only) ----------------
__device__ __forceinline__ uint32_t smem_u32(const void* p) {
    uint32_t a;
    asm("{ .reg .u64 t; cvta.to.shared.u64 t, %1; cvt.u32.u64 %0, t; }" : "=r"(a) : "l"(p));
    return a;
}
__device__ __forceinline__ void cp_async16(uint32_t dst, const void* src, int szbytes) {
    asm volatile("cp.async.cg.shared.global [%0], [%1], 16, %2;" :: "r"(dst), "l"(src), "r"(szbytes));
}
__device__ __forceinline__ void cp_commit() { asm volatile("cp.async.commit_group;" ::: "memory"); }
template<int N> __device__ __forceinline__ void cp_wait() { asm volatile("cp.async.wait_group %0;" :: "n"(N) : "memory"); }

__device__ __forceinline__ void ldsm_x4(uint32_t& r0, uint32_t& r1, uint32_t& r2, uint32_t& r3, uint32_t addr) {
    asm volatile("ldmatrix.sync.aligned.m8n8.x4.shared.b16 {%0,%1,%2,%3}, [%4];"
                 : "=r"(r0), "=r"(r1), "=r"(r2), "=r"(r3) : "r"(addr));
}
// fp16 MMA, fp32 accumulate
__device__ __forceinline__ void mma16816(float* c, const uint32_t* a, uint32_t b0, uint32_t b1) {
    asm volatile("mma.sync.aligned.m16n8k16.row.col.f32.f16.f16.f32 "
                 "{%0,%1,%2,%3}, {%4,%5,%6,%7}, {%8,%9}, {%0,%1,%2,%3};"
                 : "+f"(c[0]), "+f"(c[1]), "+f"(c[2]), "+f"(c[3])
                 : "r"(a[0]), "r"(a[1]), "r"(a[2]), "r"(a[3]), "r"(b0), "r"(b1));
}

#define SW128(o) ((o) ^ (((o) >> 3) & 0x70))

// ---------------- fp16 GEMM (fp32 accumulate) — identical to R12 ----------------
template<int BM, int BN, int WN> struct GCfg {
    static constexpr int WRN = BM / 64;
    static constexpr int WCN = BN / WN;
    static constexpr int NT  = WRN * WCN * 32;   // 128
    static constexpr int OCC = (BM == 64) ? 3 : 2;
    static constexpr int STAGE = (BM + BN) * 128;
    static constexpr int SMEM  = 3 * STAGE;
    static constexpr int NJ = WN / 8;
    static constexpr int NB = WN / 16;
};

template<int BM, int BN, int WN, bool GELU_, bool RES_, bool WF_, bool WH_>
__global__ void __launch_bounds__((GCfg<BM,BN,WN>::NT), (GCfg<BM,BN,WN>::OCC))
mma_gemm(const __half* __restrict__ A, const __half* __restrict__ Bm,
         const float* __restrict__ bias, const float* __restrict__ res,
         float* __restrict__ C, __half* __restrict__ Ch, int M, int N, int K)
{
    using CFG = GCfg<BM, BN, WN>;
    constexpr int NT = CFG::NT, STAGE = CFG::STAGE, WRN = CFG::WRN;
    constexpr int NJ = CFG::NJ, NB = CFG::NB;

    extern __shared__ __align__(1024) char smem_raw[];
    const uint32_t sb = smem_u32(smem_raw);
    const int tid = threadIdx.x, wid = tid >> 5, lane = tid & 31;
    const int bm = blockIdx.x * BM, bn = blockIdx.y * BN;
    const int wr = (WRN == 1) ? 0 : (wid & (WRN - 1));
    const int wc = (WRN == 1) ? wid : (wid >> 1);
    const int rl = lane & 15, qh = lane >> 4;

    float acc[4][NJ][4];
#pragma unroll
    for (int i = 0; i < 4; i++)
#pragma unroll
        for (int j = 0; j < NJ; j++)
#pragma unroll
            for (int r = 0; r < 4; r++) acc[i][j][r] = 0.0f;

    auto load_chunk = [&](int c, int stage) {
        const int k0 = c << 6;
        const uint32_t sA = sb + (uint32_t)stage * STAGE;
        const uint32_t sB = sA + BM * 128;
#pragma unroll
        for (int ch = tid; ch < BM * 8; ch += NT) {
            const int r = ch >> 3, qd = ch & 7;
            cp_async16(sA + SW128((uint32_t)(r * 128 + qd * 16)),
                       A + (size_t)(bm + r) * K + k0 + qd * 8, 16);
        }
#pragma unroll
        for (int ch = tid; ch < BN * 8; ch += NT) {
            const int r = ch >> 3, qd = ch & 7;
            const int gn = bn + r;
            const int vn = gn < N ? gn : N - 1;
            const int vsz = gn < N ? 16 : 0;
            cp_async16(sB + SW128((uint32_t)(r * 128 + qd * 16)),
                       Bm + (size_t)vn * K + k0 + qd * 8, vsz);
        }
    };

    const int NC = K >> 6;
    load_chunk(0, 0);
    cp_commit();
    if (NC > 1) { load_chunk(1, 1); cp_commit(); }

    int buf = 0, nxt = 2;
    for (int c = 0; c < NC; c++) {
        if (c + 1 < NC) cp_wait<1>(); else cp_wait<0>();
        __syncthreads();

        if (c + 2 < NC) { load_chunk(c + 2, nxt); cp_commit(); }

        const uint32_t tA = sb + (uint32_t)buf * STAGE;
        const uint32_t tB = tA + BM * 128;
#pragma unroll
        for (int k16 = 0; k16 < 4; k16++) {
            uint32_t a[4][4], b[NB][4];
#pragma unroll
            for (int i = 0; i < 4; i++) {
                const uint32_t off = SW128((uint32_t)((wr * 64 + i * 16 + rl) * 128 + (k16 * 2 + qh) * 16));
                ldsm_x4(a[i][0], a[i][1], a[i][2], a[i][3], tA + off);
            }
#pragma unroll
            for (int g = 0; g < NB; g++) {
                const uint32_t off = SW128((uint32_t)((wc * WN + g * 16 + rl) * 128 + (k16 * 2 + qh) * 16));
                ldsm_x4(b[g][0], b[g][1], b[g][2], b[g][3], tB + off);
            }
#pragma unroll
            for (int i = 0; i < 4; i++)
#pragma unroll
                for (int j = 0; j < NJ; j++)
                    mma16816(acc[i][j], a[i], b[j >> 1][j & 1], b[j >> 1][(j & 1) + 2]);
        }

        buf = buf == 2 ? 0 : buf + 1;
        nxt = nxt == 2 ? 0 : nxt + 1;
    }

    const int quad = lane >> 2, tq = lane & 3;
#pragma unroll
    for (int i = 0; i < 4; i++) {
        const int m0 = bm + wr * 64 + i * 16 + quad;
#pragma unroll
        for (int j = 0; j < NJ; j++) {
            const int n0 = bn + wc * WN + j * 8 + tq * 2;
#pragma unroll
            for (int half = 0; half < 2; half++) {
                const int m = m0 + half * 8;
                float c0 = acc[i][j][half * 2 + 0];
                float c1 = acc[i][j][half * 2 + 1];
                if (bias) { c0 += bias[n0]; c1 += bias[n0 + 1]; }
                if (GELU_) {
                    c0 = 0.5f * c0 * (1.0f + erff(c0 * 0.70710678118654752f));
                    c1 = 0.5f * c1 * (1.0f + erff(c1 * 0.70710678118654752f));
                }
                if (RES_) {
                    c0 += res[(size_t)m * N + n0];
                    c1 += res[(size_t)m * N + n0 + 1];
                }
                if (WF_) {
                    if (n0 < N)     C[(size_t)m * N + n0]     = c0;
                    if (n0 + 1 < N) C[(size_t)m * N + n0 + 1] = c1;
                }
                if (WH_) {
                    if (n0 < N)     Ch[(size_t)m * N + n0]     = __float2half(c0);
                    if (n0 + 1 < N) Ch[(size_t)m * N + n0 + 1] = __float2half(c1);
                }
            }
        }
    }
}

// ---------------- weight prep (transpose + fp16) ----------------
__global__ void __launch_bounds__(256) tDD_kernel(
    const float* __restrict__ wq, const float* __restrict__ wk,
    const float* __restrict__ wv, const float* __restrict__ wo,
    const float* __restrict__ bq, const float* __restrict__ bk,
    const float* __restrict__ bv, __half* __restrict__ wH, float* __restrict__ bqkv)
{
    __shared__ float tile[32][33];
    const int m = blockIdx.z, l = m >> 2, which = m & 3;
    const float* W = (which == 0 ? wq : which == 1 ? wk : which == 2 ? wv : wo)
                     + (size_t)l * D_ * D_;
    __half* WT = wH + (size_t)l * LAYER_WELEMS + (size_t)which * D_ * D_;
    const int tx = threadIdx.x & 31, ty = threadIdx.x >> 5;
    const int k0 = blockIdx.y << 5, n0 = blockIdx.x << 5;
#pragma unroll
    for (int i = 0; i < 4; i++)
        tile[ty + i * 8][tx] = W[(size_t)(k0 + ty + i * 8) * D_ + n0 + tx];
    __syncthreads();
#pragma unroll
    for (int i = 0; i < 4; i++)
        WT[(size_t)(n0 + ty + i * 8) * D_ + k0 + tx] = __float2half(tile[tx][ty + i * 8]);
    if (blockIdx.y == 0 && which < 3 && threadIdx.x < 32) {
        const float* bsrc = which == 0 ? bq : which == 1 ? bk : bv;
        bqkv[l * QKV3 + which * D_ + n0 + threadIdx.x] = bsrc[l * D_ + n0 + threadIdx.x];
    }
}

__global__ void __launch_bounds__(256) tFF_kernel(
    const float* __restrict__ w1, const float* __restrict__ w2, __half* __restrict__ wH)
{
    __shared__ float tile[32][33];
    const int l = blockIdx.z;
    const int tx = threadIdx.x & 31, ty = threadIdx.x >> 5;
    const float* W; __half* WT; int Kd, Nd, k0, n0;
    if (blockIdx.y < 32) {
        W = w1 + (size_t)l * D_ * DFF_;
        WT = wH + (size_t)l * LAYER_WELEMS + (size_t)4 * D_ * D_;
        Kd = D_; Nd = DFF_;
        k0 = blockIdx.y << 5; n0 = blockIdx.x << 5;
    } else {
        const int id = blockIdx.x + ((blockIdx.y - 32) << 7);
        W = w2 + (size_t)l * DFF_ * D_;
        WT = wH + (size_t)l * LAYER_WELEMS + (size_t)4 * D_ * D_ + (size_t)D_ * DFF_;
        Kd = DFF_; Nd = D_;
        k0 = (id >> 5) << 5; n0 = (id & 31) << 5;
    }
#pragma unroll
    for (int i = 0; i < 4; i++)
        tile[ty + i * 8][tx] = W[(size_t)(k0 + ty + i * 8) * Nd + n0 + tx];
    __syncthreads();
#pragma unroll
    for (int i = 0; i < 4; i++)
        WT[(size_t)(n0 + ty + i * 8) * Kd + k0 + tx] = __float2half(tile[tx][ty + i * 8]);
}

// elementwise fp32 -> fp16 (te -> teH); n % 4 == 0
__global__ void __launch_bounds__(256) h2_kernel(
    const float* __restrict__ x, __half* __restrict__ r, int n)
{
    const int i = (blockIdx.x * 256 + threadIdx.x) * 4;
    if (i >= n) return;
    const float4 v = *(const float4*)(x + i);
    *(__half2*)(r + i)     = __floats2half2_rn(v.x, v.y);
    *(__half2*)(r + i + 2) = __floats2half2_rn(v.z, v.w);
}

// ---------------- embedding (x fp32 + xh fp16) ----------------
__global__ void __launch_bounds__(256) embed_kernel(
    const int* __restrict__ idx, const float* __restrict__ te,
    const float* __restrict__ pe, float* __restrict__ x, __half* __restrict__ xh)
{
    const int bs = blockIdx.x;
    const int s  = bs & (S_ - 1);
    const int tok = idx[bs];
    const float4* tr = (const float4*)(te + (size_t)tok * D_);
    const float4* pr = (const float4*)(pe + (size_t)s * D_);
    float4* xo = (float4*)(x + (size_t)bs * D_);
    __half* xho = xh + (size_t)bs * D_;
    for (int i = threadIdx.x; i < D_ / 4; i += blockDim.x) {
        float4 t = tr[i], p = pr[i];
        float4 s4 = make_float4(t.x + p.x, t.y + p.y, t.z + p.z, t.w + p.w);
        xo[i] = s4;
        *(__half2*)(xho + i * 4)     = __floats2half2_rn(s4.x, s4.y);
        *(__half2*)(xho + i * 4 + 2) = __floats2half2_rn(s4.z, s4.w);
    }
}

// ---------------- layernorm (fp32 in, fp16 out) ----------------
__device__ __forceinline__ float block_reduce_sum(float val, float* sh) {
    const int lane = threadIdx.x & 31;
    const int wid  = threadIdx.x >> 5;
#pragma unroll
    for (int o = 16; o; o >>= 1) val += __shfl_down_sync(0xffffffffu, val, o);
    if (lane == 0) sh[wid] = val;
    __syncthreads();
    const int nw = (blockDim.x + 31) >> 5;
    val = (threadIdx.x < nw) ? sh[threadIdx.x] : 0.0f;
    if (wid == 0) {
#pragma unroll
        for (int o = 16; o; o >>= 1) val += __shfl_down_sync(0xffffffffu, val, o);
        if (lane == 0) sh[0] = val;
    }
    __syncthreads();
    val = sh[0];
    __syncthreads();
    return val;
}

__global__ void __launch_bounds__(256) ln_kernel(
    const float* __restrict__ x, const float* __restrict__ g,
    const float* __restrict__ bta, __half* __restrict__ out)
{
    __shared__ float red[32];
    const int row = blockIdx.x;
    const float* xr = x + (size_t)row * D_;
    float s = 0.0f, s2 = 0.0f;
    for (int i = threadIdx.x; i < D_; i += 256) {
        float v = xr[i];
        s += v; s2 += v * v;
    }
    s  = block_reduce_sum(s,  red);
    s2 = block_reduce_sum(s2, red);
    const float mean = s * (1.0f / D_);
    const float var  = s2 * (1.0f / D_) - mean * mean;
    const float rstd = rsqrtf(var + 1e-5f);
    __half* orow = out + (size_t)row * D_;
    for (int i = threadIdx.x; i < D_; i += 256)
        orow[i] = __float2half((xr[i] - mean) * rstd * g[i] + bta[i]);
}

// ---------------- flash attention: 32 queries/block, single pass ----------------
// 256 threads = 8 warps; warp w owns queries s0 + w*4 .. +3 (s uniform per warp).
// Online softmax: running max m, sum l, rescaled accumulator. K/V tiles of 128
// rows staged once per block (fp16 -> fp32 smem, stride 68 = conflict-light).
// smem: Kb[128*68] + Vb[128*68] + P[32*132] + qs[32*64] = 94720 B -> occ 2.
#define FQ 32
#define FT 128
#define AT_STR 68
#define AT_P  (2 * FT * AT_STR)
#define AT_Q  (AT_P + FQ * 132)
#define ATT_SMEM ((AT_Q + FQ * DK_) * 4)   // 94720 B

__global__ void __launch_bounds__(256, 2) attn_kernel(
    const __half* __restrict__ qkv, __half* __restrict__ y)
{
    extern __shared__ float sm[];
    float* Kb = sm;
    float* Vb = sm + FT * AT_STR;
    float* P  = sm + AT_P;
    float* qs = sm + AT_Q;
    const int tid = threadIdx.x, wid = tid >> 5, lane = tid & 31;
    const int s0 = blockIdx.x * FQ;
    const int h = blockIdx.y, b = blockIdx.z;
    const size_t base = (size_t)b * S_ * QKV3 + (size_t)h * DK_;
    const __half* qp = qkv + base;
    const __half* kp = qkv + base + D_;
    const __half* vp = qkv + base + 2 * D_;

    // load 32 query rows (fp16 -> fp32 smem)
    for (int i = tid; i < FQ * DK_ / 2; i += 256) {
        const int row = i >> 5, col = (i & 31) * 2;
        const float2 qv = __half22float2(*(const __half2*)(qp + (size_t)(s0 + row) * QKV3 + col));
        qs[row * DK_ + col] = qv.x;
        qs[row * DK_ + col + 1] = qv.y;
    }

    const int qb = wid * 4;         // first query of this warp (block-local)
    const int dd = lane * 2;        // dims owned by this lane
    float m[4], lsum[4], acc[4][2];
#pragma unroll
    for (int q = 0; q < 4; q++) {
        m[q] = -INFINITY; lsum[q] = 0.0f;
        acc[q][0] = 0.0f; acc[q][1] = 0.0f;
    }

    const int smaxb = s0 + FQ - 1;
    const int ntiles = (smaxb + FT) / FT;   // ceil((smaxb+1)/128)

    for (int tI = 0; tI < ntiles; tI++) {
        const int c0 = tI * FT;
        __syncthreads();
        // stage K and V tiles (128 rows x 64 halves each)
#pragma unroll
        for (int i = 0; i < 8; i++) {
            const int ch = tid + (i << 8);           // 0..2047
            const int row = ch >> 4, q4 = (ch & 15) * 4;
            const __half2* sK = (const __half2*)(kp + (size_t)(c0 + row) * QKV3 + q4);
            const float2 k0f = __half22float2(sK[0]);
            const float2 k1f = __half22float2(sK[1]);
            float* dk = Kb + row * AT_STR + q4;
            dk[0] = k0f.x; dk[1] = k0f.y; dk[2] = k1f.x; dk[3] = k1f.y;
            const __half2* sV = (const __half2*)(vp + (size_t)(c0 + row) * QKV3 + q4);
            const float2 v0f = __half22float2(sV[0]);
            const float2 v1f = __half22float2(sV[1]);
            float* dv = Vb + row * AT_STR + q4;
            dv[0] = v0f.x; dv[1] = v0f.y; dv[2] = v1f.x; dv[3] = v1f.y;
        }
        __syncthreads();

#pragma unroll
        for (int q = 0; q < 4; q++) {
            const int s = s0 + qb + q;               // warp-uniform
            const int lim = min(FT, s + 1 - c0);
            if (lim <= 0) continue;                  // warp-uniform branch
            const float* qrow = qs + (qb + q) * DK_;
            float* prow = P + (qb + q) * 132;

            // scores (lanes stride keys)
            float mloc = -INFINITY;
            for (int k = lane; k < lim; k += 32) {
                const float* kr = Kb + k * AT_STR;
                float d = 0.0f;
#pragma unroll
                for (int i = 0; i < DK_; i += 4) {
                    const float4 kv = *(const float4*)(kr + i);
                    d += qrow[i] * kv.x + qrow[i + 1] * kv.y
                       + qrow[i + 2] * kv.z + qrow[i + 3] * kv.w;
                }
                d *= 0.125f;
                prow[k] = d;
                mloc = fmaxf(mloc, d);
            }
#pragma unroll
            for (int o = 16; o; o >>= 1) mloc = fmaxf(mloc, __shfl_xor_sync(0xffffffffu, mloc, o));

            const float mnew = fmaxf(m[q], mloc);
            const float scale = expf(m[q] - mnew);   // m=-inf first tile -> 0
            float ls = 0.0f;
            for (int k = lane; k < lim; k += 32) {
                const float e = expf(prow[k] - mnew);
                prow[k] = e;
                ls += e;
            }
#pragma unroll
            for (int o = 16; o; o >>= 1) ls += __shfl_xor_sync(0xffffffffu, ls, o);
            lsum[q] = lsum[q] * scale + ls;
            acc[q][0] *= scale;
            acc[q][1] *= scale;
            m[q] = mnew;
            __syncwarp();

            // V accumulation (all lanes read all p; each lane owns 2 dims)
            float a0 = 0.0f, a1 = 0.0f, b0 = 0.0f, b1 = 0.0f;
            int k = 0;
            for (; k + 2 <= lim; k += 2) {
                const float p0 = prow[k], p1 = prow[k + 1];
                const float2 v0 = *(const float2*)(Vb + k * AT_STR + dd);
                const float2 v1 = *(const float2*)(Vb + (k + 1) * AT_STR + dd);
                a0 += p0 * v0.x; a1 += p0 * v0.y;
                b0 += p1 * v1.x; b1 += p1 * v1.y;
            }
            for (; k < lim; k++) {
                const float p = prow[k];
                const float2 v0 = *(const float2*)(Vb + k * AT_STR + dd);
                a0 += p * v0.x; a1 += p * v0.y;
            }
            acc[q][0] += a0 + b0;
            acc[q][1] += a1 + b1;
            __syncwarp();
        }
    }

    // write out (fp16, y layout [b][s][h*64+dim])
#pragma unroll
    for (int q = 0; q < 4; q++) {
        const int s = s0 + qb + q;
        const float inv = 1.0f / lsum[q];
        *(__half2*)(y + (size_t)b * S_ * D_ + (size_t)h * DK_ + (size_t)s * D_ + dd) =
            __floats2half2_rn(acc[q][0] * inv, acc[q][1] * inv);
    }
}

// ---------------- driver ----------------
extern "C" void kernel_launch(void* const* d_in, const int* in_sizes, int n_in,
                              void* d_out, int out_size)
{
    const int*   idx   = (const int*)  d_in[0];
    const float* te    = (const float*)d_in[1];
    const float* pe    = (const float*)d_in[2];
    const float* wq    = (const float*)d_in[3];
    const float* bq    = (const float*)d_in[4];
    const float* wk    = (const float*)d_in[5];
    const float* bk    = (const float*)d_in[6];
    const float* wv    = (const float*)d_in[7];
    const float* bv    = (const float*)d_in[8];
    const float* wo    = (const float*)d_in[9];
    const float* bo    = (const float*)d_in[10];
    const float* ln2g  = (const float*)d_in[11];
    const float* ln2b  = (const float*)d_in[12];
    const float* w1    = (const float*)d_in[13];
    const float* b1    = (const float*)d_in[14];
    const float* w2    = (const float*)d_in[15];
    const float* b2    = (const float*)d_in[16];
    const float* lnfg  = (const float*)d_in[17];
    const float* lnfb  = (const float*)d_in[18];
    float* out = (float*)d_out;

    float *x, *bqkv;
    __half *xh, *qkv, *y, *t, *hb, *wH, *teH;
    cudaGetSymbolAddress((void**)&x,    g_x);
    cudaGetSymbolAddress((void**)&xh,   g_xh);
    cudaGetSymbolAddress((void**)&qkv,  g_qkv);
    cudaGetSymbolAddress((void**)&y,    g_y);
    cudaGetSymbolAddress((void**)&t,    g_t);
    cudaGetSymbolAddress((void**)&hb,   g_h);
    cudaGetSymbolAddress((void**)&wH,   g_wH);
    cudaGetSymbolAddress((void**)&bqkv, g_bqkv);
    cudaGetSymbolAddress((void**)&teH,  g_teH);

    constexpr int SMW = GCfg<128, 128, 64>::SMEM;   // 96 KB (WIDE)
    constexpr int SMS = GCfg<64, 128, 32>::SMEM;    // 72 KB (SMALLM)
    cudaFuncSetAttribute(mma_gemm<128, 128, 64, false, false, false, true >, cudaFuncAttributeMaxDynamicSharedMemorySize, SMW);
    cudaFuncSetAttribute(mma_gemm<128, 128, 64, true , false, false, true >, cudaFuncAttributeMaxDynamicSharedMemorySize, SMW);
    cudaFuncSetAttribute(mma_gemm<128, 128, 64, false, false, true , false>, cudaFuncAttributeMaxDynamicSharedMemorySize, SMW);
    cudaFuncSetAttribute(mma_gemm<64, 128, 32, false, true , true , false>, cudaFuncAttributeMaxDynamicSharedMemorySize, SMS);
    cudaFuncSetAttribute(mma_gemm<64, 128, 32, false, true , true , true >, cudaFuncAttributeMaxDynamicSharedMemorySize, SMS);
    cudaFuncSetAttribute(attn_kernel, cudaFuncAttributeMaxDynamicSharedMemorySize, ATT_SMEM);

    const int M = M_TOK;

    // prep
    embed_kernel<<<M, 256>>>(idx, te, pe, x, xh);
    tDD_kernel<<<dim3(32, 32, 4 * L_), 256>>>(wq, wk, wv, wo, bq, bk, bv, wH, bqkv);
    tFF_kernel<<<dim3(128, 64, L_), 256>>>(w1, w2, wH);

    // grids
    const dim3 gQKV(M / 128, QKV3 / 128);        // 16 x 24  (WIDE)
    const dim3 gW1 (M / 128, DFF_ / 128);        // 16 x 32  (WIDE)
    const dim3 gSM (M / 64, D_ / 128);           // 32 x 8   (SMALLM)
    const dim3 gLM (M / 128, (V_ + 127) / 128);  // 16 x 393 (WIDE)
    const dim3 gAT (S_ / FQ, H_, B_);            // 32 x 16 x 2

    for (int l = 0; l < L_; l++) {
        const size_t lw = (size_t)l * LAYER_WELEMS;
        const __half *wqkvT = wH + lw;
        const __half *woT   = wH + lw + 3 * D_ * D_;
        const __half *w1T   = wH + lw + 4 * D_ * D_;
        const __half *w2T   = w1T + (size_t)D_ * DFF_;

        // qkv(fp16) = xh @ [Wq|Wk|Wv] + bqkv
        mma_gemm<128, 128, 64, false, false, false, true><<<gQKV, 128, SMW>>>(
            xh, wqkvT, bqkv + l * QKV3, nullptr, nullptr, qkv, M, QKV3, D_);

        attn_kernel<<<gAT, 256, ATT_SMEM>>>(qkv, y);

        // x(fp32) = x + y@Wo + bo
        mma_gemm<64, 128, 32, false, true, true, false><<<gSM, 128, SMS>>>(
            y, woT, bo + (size_t)l * D_, x, x, nullptr, M, D_, D_);

        // t(fp16) = LN(x)
        ln_kernel<<<M, 256>>>(x, ln2g + (size_t)l * D_, ln2b + (size_t)l * D_, t);

        // hb(fp16) = gelu(t@W1 + b1)
        mma_gemm<128, 128, 64, true, false, false, true><<<gW1, 128, SMW>>>(
            t, w1T, b1 + (size_t)l * DFF_, nullptr, nullptr, hb, M, DFF_, D_);

        // x(fp32) = x + hb@W2 + b2 ; xh(fp16) = x
        mma_gemm<64, 128, 32, false, true, true, true><<<gSM, 128, SMS>>>(
            hb, w2T, b2 + (size_t)l * D_, x, x, xh, M, D_, DFF_);
    }

    // final LN + weight-tied LM head
    ln_kernel<<<M, 256>>>(x, lnfg, lnfb, t);
    h2_kernel<<<(V_ * D_ / 4 + 255) / 256, 256>>>(te, teH, V_ * D_);
    mma_gemm<128, 128, 64, false, false, true, false><<<gLM, 128, SMW>>>(
        t, teH, nullptr, nullptr, out, nullptr, M, V_, D_);
}

// round 14
// speedup vs baseline: 1.0236x; 1.0236x over previous
#include <cuda_runtime.h>
#include <cuda_fp16.h>
#include <math.h>
#include <stdint.h>

// Problem constants
#define B_ 2
#define S_ 1024
#define D_ 1024
#define H_ 16
#define DK_ 64
#define DFF_ 4096
#define L_ 4
#define V_ 50257
#define M_TOK (B_ * S_)   // 2048 rows
#define QKV3 (3 * D_)     // 3072

// ---------------- scratch (static device globals; no allocation allowed) ----
__device__ float  g_x[M_TOK * D_];        // residual stream (fp32)
__device__ __half g_xh[M_TOK * D_];       // fp16 copy of x (QKV A input)
__device__ __half g_qkv[M_TOK * QKV3];    // fused q|k|v (fp16)
__device__ __half g_y[M_TOK * D_];        // attention out (fp16)
__device__ __half g_t[M_TOK * D_];        // ln out (fp16)
__device__ __half g_h[M_TOK * DFF_];      // mlp hidden (fp16)

// transposed fp16 weights: per layer [wqT][wkT][wvT][woT][w1T][w2T]
#define LAYER_WELEMS (4 * D_ * D_ + D_ * DFF_ + DFF_ * D_)
__device__ __half g_wH[(size_t)L_ * LAYER_WELEMS];
__device__ float  g_bqkv[L_ * QKV3];       // packed qkv bias (fp32)
__device__ __half g_teH[(size_t)V_ * D_];  // fp16 token embedding ([V,D]=[N,K])

// ---------------- PTX helpers (sm_80+ portable only) ----------------
__device__ __forceinline__ uint32_t smem_u32(const void* p) {
    uint32_t a;
    asm("{ .reg .u64 t; cvta.to.shared.u64 t, %1; cvt.u32.u64 %0, t; }" : "=r"(a) : "l"(p));
    return a;
}
__device__ __forceinline__ void cp_async16(uint32_t dst, const void* src, int szbytes) {
    asm volatile("cp.async.cg.shared.global [%0], [%1], 16, %2;" :: "r"(dst), "l"(src), "r"(szbytes));
}
__device__ __forceinline__ void cp_commit() { asm volatile("cp.async.commit_group;" ::: "memory"); }
template<int N> __device__ __forceinline__ void cp_wait() { asm volatile("cp.async.wait_group %0;" :: "n"(N) : "memory"); }

__device__ __forceinline__ void ldsm_x4(uint32_t& r0, uint32_t& r1, uint32_t& r2, uint32_t& r3, uint32_t addr) {
    asm volatile("ldmatrix.sync.aligned.m8n8.x4.shared.b16 {%0,%1,%2,%3}, [%4];"
                 : "=r"(r0), "=r"(r1), "=r"(r2), "=r"(r3) : "r"(addr));
}
// fp16 MMA, fp32 accumulate
__device__ __forceinline__ void mma16816(float* c, const uint32_t* a, uint32_t b0, uint32_t b1) {
    asm volatile("mma.sync.aligned.m16n8k16.row.col.f32.f16.f16.f32 "
                 "{%0,%1,%2,%3}, {%4,%5,%6,%7}, {%8,%9}, {%0,%1,%2,%3};"
                 : "+f"(c[0]), "+f"(c[1]), "+f"(c[2]), "+f"(c[3])
                 : "r"(a[0]), "r"(a[1]), "r"(a[2]), "r"(a[3]), "r"(b0), "r"(b1));
}

#define SW128(o) ((o) ^ (((o) >> 3) & 0x70))

// ---------------- fp16 GEMM (fp32 accumulate) ----------------
// C[M,N] = act( A[M,K] @ B[N,K]^T + bias ) (+ res)
// CTA BM x BN, BK=64 halves (128B SW128 rows), 3-stage cp.async.
// Warp tile 64 x WN; warps = (BM/64) x (BN/WN); 128 threads.
//   WIDE   : 128x128, WN=64 -> 2x2 warps, occ 2  (W1, LM head)
//   SMALLM : 64x128,  WN=32 -> 1x4 warps, occ 3  (QKV: 768 CTAs, 86% wave eff)
//   SMALL64: 64x64,   WN=16 -> 1x4 warps, occ 4  (Wo/W2: 512 CTAs on 592 slots)
// Grid: blockIdx.x = M-block (fastest, B-tile L2 reuse), blockIdx.y = N-block.
// M % BM == 0, K % 64 == 0; N tail OK (clamp+zfill, scalar store guard).
// WF_: write fp32 C.  WH_: write fp16 Ch.

template<int BM, int BN, int WN> struct GCfg {
    static constexpr int WRN = BM / 64;
    static constexpr int WCN = BN / WN;
    static constexpr int NT  = WRN * WCN * 32;   // 128
    static constexpr int OCC = (BM == 64) ? ((BN == 64) ? 4 : 3) : 2;
    static constexpr int STAGE = (BM + BN) * 128;
    static constexpr int SMEM  = 3 * STAGE;
    static constexpr int NJ = WN / 8;
    static constexpr int NB = WN / 16;
};

template<int BM, int BN, int WN, bool GELU_, bool RES_, bool WF_, bool WH_>
__global__ void __launch_bounds__((GCfg<BM,BN,WN>::NT), (GCfg<BM,BN,WN>::OCC))
mma_gemm(const __half* __restrict__ A, const __half* __restrict__ Bm,
         const float* __restrict__ bias, const float* __restrict__ res,
         float* __restrict__ C, __half* __restrict__ Ch, int M, int N, int K)
{
    using CFG = GCfg<BM, BN, WN>;
    constexpr int NT = CFG::NT, STAGE = CFG::STAGE, WRN = CFG::WRN;
    constexpr int NJ = CFG::NJ, NB = CFG::NB;

    extern __shared__ __align__(1024) char smem_raw[];
    const uint32_t sb = smem_u32(smem_raw);
    const int tid = threadIdx.x, wid = tid >> 5, lane = tid & 31;
    const int bm = blockIdx.x * BM, bn = blockIdx.y * BN;
    const int wr = (WRN == 1) ? 0 : (wid & (WRN - 1));
    const int wc = (WRN == 1) ? wid : (wid >> 1);
    const int rl = lane & 15, qh = lane >> 4;

    float acc[4][NJ][4];
#pragma unroll
    for (int i = 0; i < 4; i++)
#pragma unroll
        for (int j = 0; j < NJ; j++)
#pragma unroll
            for (int r = 0; r < 4; r++) acc[i][j][r] = 0.0f;

    auto load_chunk = [&](int c, int stage) {
        const int k0 = c << 6;
        const uint32_t sA = sb + (uint32_t)stage * STAGE;
        const uint32_t sB = sA + BM * 128;
#pragma unroll
        for (int ch = tid; ch < BM * 8; ch += NT) {
            const int r = ch >> 3, qd = ch & 7;
            cp_async16(sA + SW128((uint32_t)(r * 128 + qd * 16)),
                       A + (size_t)(bm + r) * K + k0 + qd * 8, 16);
        }
#pragma unroll
        for (int ch = tid; ch < BN * 8; ch += NT) {
            const int r = ch >> 3, qd = ch & 7;
            const int gn = bn + r;
            const int vn = gn < N ? gn : N - 1;
            const int vsz = gn < N ? 16 : 0;
            cp_async16(sB + SW128((uint32_t)(r * 128 + qd * 16)),
                       Bm + (size_t)vn * K + k0 + qd * 8, vsz);
        }
    };

    const int NC = K >> 6;
    load_chunk(0, 0);
    cp_commit();
    if (NC > 1) { load_chunk(1, 1); cp_commit(); }

    int buf = 0, nxt = 2;
    for (int c = 0; c < NC; c++) {
        if (c + 1 < NC) cp_wait<1>(); else cp_wait<0>();
        __syncthreads();

        if (c + 2 < NC) { load_chunk(c + 2, nxt); cp_commit(); }

        const uint32_t tA = sb + (uint32_t)buf * STAGE;
        const uint32_t tB = tA + BM * 128;
#pragma unroll
        for (int k16 = 0; k16 < 4; k16++) {
            uint32_t a[4][4], b[NB][4];
#pragma unroll
            for (int i = 0; i < 4; i++) {
                const uint32_t off = SW128((uint32_t)((wr * 64 + i * 16 + rl) * 128 + (k16 * 2 + qh) * 16));
                ldsm_x4(a[i][0], a[i][1], a[i][2], a[i][3], tA + off);
            }
#pragma unroll
            for (int g = 0; g < NB; g++) {
                const uint32_t off = SW128((uint32_t)((wc * WN + g * 16 + rl) * 128 + (k16 * 2 + qh) * 16));
                ldsm_x4(b[g][0], b[g][1], b[g][2], b[g][3], tB + off);
            }
            // B fragment pairing (m16n8k16): n-tile o of group g uses {b[g][o], b[g][o+2]}
#pragma unroll
            for (int i = 0; i < 4; i++)
#pragma unroll
                for (int j = 0; j < NJ; j++)
                    mma16816(acc[i][j], a[i], b[j >> 1][j & 1], b[j >> 1][(j & 1) + 2]);
        }

        buf = buf == 2 ? 0 : buf + 1;
        nxt = nxt == 2 ? 0 : nxt + 1;
    }

    const int quad = lane >> 2, tq = lane & 3;
#pragma unroll
    for (int i = 0; i < 4; i++) {
        const int m0 = bm + wr * 64 + i * 16 + quad;
#pragma unroll
        for (int j = 0; j < NJ; j++) {
            const int n0 = bn + wc * WN + j * 8 + tq * 2;
#pragma unroll
            for (int half = 0; half < 2; half++) {
                const int m = m0 + half * 8;
                float c0 = acc[i][j][half * 2 + 0];
                float c1 = acc[i][j][half * 2 + 1];
                if (bias) { c0 += bias[n0]; c1 += bias[n0 + 1]; }
                if (GELU_) {
                    c0 = 0.5f * c0 * (1.0f + erff(c0 * 0.70710678118654752f));
                    c1 = 0.5f * c1 * (1.0f + erff(c1 * 0.70710678118654752f));
                }
                if (RES_) {
                    c0 += res[(size_t)m * N + n0];
                    c1 += res[(size_t)m * N + n0 + 1];
                }
                if (WF_) {
                    if (n0 < N)     C[(size_t)m * N + n0]     = c0;
                    if (n0 + 1 < N) C[(size_t)m * N + n0 + 1] = c1;
                }
                if (WH_) {
                    if (n0 < N)     Ch[(size_t)m * N + n0]     = __float2half(c0);
                    if (n0 + 1 < N) Ch[(size_t)m * N + n0 + 1] = __float2half(c1);
                }
            }
        }
    }
}

// ---------------- weight prep (transpose + fp16) ----------------
__global__ void __launch_bounds__(256) tDD_kernel(
    const float* __restrict__ wq, const float* __restrict__ wk,
    const float* __restrict__ wv, const float* __restrict__ wo,
    const float* __restrict__ bq, const float* __restrict__ bk,
    const float* __restrict__ bv, __half* __restrict__ wH, float* __restrict__ bqkv)
{
    __shared__ float tile[32][33];
    const int m = blockIdx.z, l = m >> 2, which = m & 3;
    const float* W = (which == 0 ? wq : which == 1 ? wk : which == 2 ? wv : wo)
                     + (size_t)l * D_ * D_;
    __half* WT = wH + (size_t)l * LAYER_WELEMS + (size_t)which * D_ * D_;
    const int tx = threadIdx.x & 31, ty = threadIdx.x >> 5;
    const int k0 = blockIdx.y << 5, n0 = blockIdx.x << 5;
#pragma unroll
    for (int i = 0; i < 4; i++)
        tile[ty + i * 8][tx] = W[(size_t)(k0 + ty + i * 8) * D_ + n0 + tx];
    __syncthreads();
#pragma unroll
    for (int i = 0; i < 4; i++)
        WT[(size_t)(n0 + ty + i * 8) * D_ + k0 + tx] = __float2half(tile[tx][ty + i * 8]);
    if (blockIdx.y == 0 && which < 3 && threadIdx.x < 32) {
        const float* bsrc = which == 0 ? bq : which == 1 ? bk : bv;
        bqkv[l * QKV3 + which * D_ + n0 + threadIdx.x] = bsrc[l * D_ + n0 + threadIdx.x];
    }
}

__global__ void __launch_bounds__(256) tFF_kernel(
    const float* __restrict__ w1, const float* __restrict__ w2, __half* __restrict__ wH)
{
    __shared__ float tile[32][33];
    const int l = blockIdx.z;
    const int tx = threadIdx.x & 31, ty = threadIdx.x >> 5;
    const float* W; __half* WT; int Kd, Nd, k0, n0;
    if (blockIdx.y < 32) {
        W = w1 + (size_t)l * D_ * DFF_;
        WT = wH + (size_t)l * LAYER_WELEMS + (size_t)4 * D_ * D_;
        Kd = D_; Nd = DFF_;
        k0 = blockIdx.y << 5; n0 = blockIdx.x << 5;
    } else {
        const int id = blockIdx.x + ((blockIdx.y - 32) << 7);
        W = w2 + (size_t)l * DFF_ * D_;
        WT = wH + (size_t)l * LAYER_WELEMS + (size_t)4 * D_ * D_ + (size_t)D_ * DFF_;
        Kd = DFF_; Nd = D_;
        k0 = (id >> 5) << 5; n0 = (id & 31) << 5;
    }
#pragma unroll
    for (int i = 0; i < 4; i++)
        tile[ty + i * 8][tx] = W[(size_t)(k0 + ty + i * 8) * Nd + n0 + tx];
    __syncthreads();
#pragma unroll
    for (int i = 0; i < 4; i++)
        WT[(size_t)(n0 + ty + i * 8) * Kd + k0 + tx] = __float2half(tile[tx][ty + i * 8]);
}

// elementwise fp32 -> fp16 (te -> teH); n % 4 == 0
__global__ void __launch_bounds__(256) h2_kernel(
    const float* __restrict__ x, __half* __restrict__ r, int n)
{
    const int i = (blockIdx.x * 256 + threadIdx.x) * 4;
    if (i >= n) return;
    const float4 v = *(const float4*)(x + i);
    *(__half2*)(r + i)     = __floats2half2_rn(v.x, v.y);
    *(__half2*)(r + i + 2) = __floats2half2_rn(v.z, v.w);
}

// ---------------- embedding (x fp32 + xh fp16) ----------------
__global__ void __launch_bounds__(256) embed_kernel(
    const int* __restrict__ idx, const float* __restrict__ te,
    const float* __restrict__ pe, float* __restrict__ x, __half* __restrict__ xh)
{
    const int bs = blockIdx.x;
    const int s  = bs & (S_ - 1);
    const int tok = idx[bs];
    const float4* tr = (const float4*)(te + (size_t)tok * D_);
    const float4* pr = (const float4*)(pe + (size_t)s * D_);
    float4* xo = (float4*)(x + (size_t)bs * D_);
    __half* xho = xh + (size_t)bs * D_;
    for (int i = threadIdx.x; i < D_ / 4; i += blockDim.x) {
        float4 t = tr[i], p = pr[i];
        float4 s4 = make_float4(t.x + p.x, t.y + p.y, t.z + p.z, t.w + p.w);
        xo[i] = s4;
        *(__half2*)(xho + i * 4)     = __floats2half2_rn(s4.x, s4.y);
        *(__half2*)(xho + i * 4 + 2) = __floats2half2_rn(s4.z, s4.w);
    }
}

// ---------------- layernorm (fp32 in, fp16 out) ----------------
__device__ __forceinline__ float block_reduce_sum(float val, float* sh) {
    const int lane = threadIdx.x & 31;
    const int wid  = threadIdx.x >> 5;
#pragma unroll
    for (int o = 16; o; o >>= 1) val += __shfl_down_sync(0xffffffffu, val, o);
    if (lane == 0) sh[wid] = val;
    __syncthreads();
    const int nw = (blockDim.x + 31) >> 5;
    val = (threadIdx.x < nw) ? sh[threadIdx.x] : 0.0f;
    if (wid == 0) {
#pragma unroll
        for (int o = 16; o; o >>= 1) val += __shfl_down_sync(0xffffffffu, val, o);
        if (lane == 0) sh[0] = val;
    }
    __syncthreads();
    val = sh[0];
    __syncthreads();
    return val;
}

__global__ void __launch_bounds__(256) ln_kernel(
    const float* __restrict__ x, const float* __restrict__ g,
    const float* __restrict__ bta, __half* __restrict__ out)
{
    __shared__ float red[32];
    const int row = blockIdx.x;
    const float* xr = x + (size_t)row * D_;
    float s = 0.0f, s2 = 0.0f;
    for (int i = threadIdx.x; i < D_; i += 256) {
        float v = xr[i];
        s += v; s2 += v * v;
    }
    s  = block_reduce_sum(s,  red);
    s2 = block_reduce_sum(s2, red);
    const float mean = s * (1.0f / D_);
    const float var  = s2 * (1.0f / D_) - mean * mean;
    const float rstd = rsqrtf(var + 1e-5f);
    __half* orow = out + (size_t)row * D_;
    for (int i = threadIdx.x; i < D_; i += 256)
        orow[i] = __float2half((xr[i] - mean) * rstd * g[i] + bta[i]);
}

// ---------------- attention: 8 queries/block, smem-tiled fp16 K/V (R12) -------
#define ATT_STRIDE 68
#define ATT_SMEM ((128 * ATT_STRIDE + 8 * S_ + 8 * DK_) * 4)   // 69632 B

__global__ void __launch_bounds__(256) attn_kernel(
    const __half* __restrict__ qkv, __half* __restrict__ y)
{
    extern __shared__ float asmem[];
    float* Kb = asmem;
    float* sp = asmem + 128 * ATT_STRIDE;
    float* qs = sp + 8 * S_;
    const int tid = threadIdx.x, wid = tid >> 5, lane = tid & 31;
    const int s0 = blockIdx.x * 8;
    const int s = s0 + wid;
    const int h = blockIdx.y, b = blockIdx.z;
    const size_t base = (size_t)b * S_ * QKV3 + (size_t)h * DK_;
    const __half* kp = qkv + base + D_;
    const __half* vp = qkv + base + 2 * D_;

    {
        const float2 qv = __half22float2(*(const __half2*)(qkv + base + (size_t)s * QKV3 + lane * 2));
        qs[wid * DK_ + lane * 2]     = qv.x;
        qs[wid * DK_ + lane * 2 + 1] = qv.y;
    }
    __syncwarp();

    const int nkmax = s0 + 8;
    float lmax = -INFINITY;

    for (int c0 = 0; c0 < nkmax; c0 += 128) {
        __syncthreads();
#pragma unroll
        for (int i = 0; i < 8; i++) {
            const int ch = tid + (i << 8);            // 0..2047
            const int row = ch >> 4, q4 = (ch & 15) * 4;
            const __half2* src = (const __half2*)(kp + (size_t)(c0 + row) * QKV3 + q4);
            const float2 f0 = __half22float2(src[0]);
            const float2 f1 = __half22float2(src[1]);
            float* dst = Kb + row * ATT_STRIDE + q4;
            dst[0] = f0.x; dst[1] = f0.y; dst[2] = f1.x; dst[3] = f1.y;
        }
        __syncthreads();
        const int lim = min(c0 + 128, s + 1);
        for (int t = c0 + lane; t < lim; t += 32) {
            const float* kr = Kb + (t - c0) * ATT_STRIDE;
            float d = 0.0f;
#pragma unroll
            for (int i = 0; i < DK_; i += 4) {
                const float4 kv = *(const float4*)(kr + i);
                d += qs[wid * DK_ + i] * kv.x + qs[wid * DK_ + i + 1] * kv.y
                   + qs[wid * DK_ + i + 2] * kv.z + qs[wid * DK_ + i + 3] * kv.w;
            }
            d *= 0.125f;
            sp[wid * S_ + t] = d;
            lmax = fmaxf(lmax, d);
        }
    }
#pragma unroll
    for (int o = 16; o; o >>= 1) lmax = fmaxf(lmax, __shfl_xor_sync(0xffffffffu, lmax, o));

    float lsum = 0.0f;
    for (int t = lane; t < s + 1; t += 32) {
        const float e = expf(sp[wid * S_ + t] - lmax);
        sp[wid * S_ + t] = e;
        lsum += e;
    }
#pragma unroll
    for (int o = 16; o; o >>= 1) lsum += __shfl_xor_sync(0xffffffffu, lsum, o);
    const float inv = 1.0f / lsum;
    __syncwarp();

    const int dd = lane * 2;
    float a0 = 0.0f, a1 = 0.0f, c0a = 0.0f, c1a = 0.0f;
    for (int c0 = 0; c0 < nkmax; c0 += 128) {
        __syncthreads();
#pragma unroll
        for (int i = 0; i < 8; i++) {
            const int ch = tid + (i << 8);
            const int row = ch >> 4, q4 = (ch & 15) * 4;
            const __half2* src = (const __half2*)(vp + (size_t)(c0 + row) * QKV3 + q4);
            const float2 f0 = __half22float2(src[0]);
            const float2 f1 = __half22float2(src[1]);
            float* dst = Kb + row * ATT_STRIDE + q4;
            dst[0] = f0.x; dst[1] = f0.y; dst[2] = f1.x; dst[3] = f1.y;
        }
        __syncthreads();
        const int lim = min(c0 + 128, s + 1);
        int t = c0;
        for (; t + 2 <= lim; t += 2) {
            const float p0 = sp[wid * S_ + t], p1 = sp[wid * S_ + t + 1];
            a0  += p0 * Kb[(t - c0) * ATT_STRIDE + dd];
            a1  += p0 * Kb[(t - c0) * ATT_STRIDE + dd + 1];
            c0a += p1 * Kb[(t + 1 - c0) * ATT_STRIDE + dd];
            c1a += p1 * Kb[(t + 1 - c0) * ATT_STRIDE + dd + 1];
        }
        for (; t < lim; t++) {
            const float p = sp[wid * S_ + t];
            a0 += p * Kb[(t - c0) * ATT_STRIDE + dd];
            a1 += p * Kb[(t - c0) * ATT_STRIDE + dd + 1];
        }
    }
    *(__half2*)(y + (size_t)b * S_ * D_ + (size_t)h * DK_ + (size_t)s * D_ + dd) =
        __floats2half2_rn((a0 + c0a) * inv, (a1 + c1a) * inv);
}

// ---------------- driver ----------------
extern "C" void kernel_launch(void* const* d_in, const int* in_sizes, int n_in,
                              void* d_out, int out_size)
{
    const int*   idx   = (const int*)  d_in[0];
    const float* te    = (const float*)d_in[1];
    const float* pe    = (const float*)d_in[2];
    const float* wq    = (const float*)d_in[3];
    const float* bq    = (const float*)d_in[4];
    const float* wk    = (const float*)d_in[5];
    const float* bk    = (const float*)d_in[6];
    const float* wv    = (const float*)d_in[7];
    const float* bv    = (const float*)d_in[8];
    const float* wo    = (const float*)d_in[9];
    const float* bo    = (const float*)d_in[10];
    const float* ln2g  = (const float*)d_in[11];
    const float* ln2b  = (const float*)d_in[12];
    const float* w1    = (const float*)d_in[13];
    const float* b1    = (const float*)d_in[14];
    const float* w2    = (const float*)d_in[15];
    const float* b2    = (const float*)d_in[16];
    const float* lnfg  = (const float*)d_in[17];
    const float* lnfb  = (const float*)d_in[18];
    float* out = (float*)d_out;

    float *x, *bqkv;
    __half *xh, *qkv, *y, *t, *hb, *wH, *teH;
    cudaGetSymbolAddress((void**)&x,    g_x);
    cudaGetSymbolAddress((void**)&xh,   g_xh);
    cudaGetSymbolAddress((void**)&qkv,  g_qkv);
    cudaGetSymbolAddress((void**)&y,    g_y);
    cudaGetSymbolAddress((void**)&t,    g_t);
    cudaGetSymbolAddress((void**)&hb,   g_h);
    cudaGetSymbolAddress((void**)&wH,   g_wH);
    cudaGetSymbolAddress((void**)&bqkv, g_bqkv);
    cudaGetSymbolAddress((void**)&teH,  g_teH);

    constexpr int SMW  = GCfg<128, 128, 64>::SMEM;   // 96 KB (WIDE)
    constexpr int SMS  = GCfg<64, 128, 32>::SMEM;    // 72 KB (SMALLM)
    constexpr int SM64 = GCfg<64, 64, 16>::SMEM;     // 48 KB (SMALL64)
    cudaFuncSetAttribute(mma_gemm<64, 128, 32, false, false, false, true >, cudaFuncAttributeMaxDynamicSharedMemorySize, SMS);
    cudaFuncSetAttribute(mma_gemm<128, 128, 64, true , false, false, true >, cudaFuncAttributeMaxDynamicSharedMemorySize, SMW);
    cudaFuncSetAttribute(mma_gemm<128, 128, 64, false, false, true , false>, cudaFuncAttributeMaxDynamicSharedMemorySize, SMW);
    cudaFuncSetAttribute(mma_gemm<64, 64, 16, false, true , true , false>, cudaFuncAttributeMaxDynamicSharedMemorySize, SM64);
    cudaFuncSetAttribute(mma_gemm<64, 64, 16, false, true , true , true >, cudaFuncAttributeMaxDynamicSharedMemorySize, SM64);
    cudaFuncSetAttribute(attn_kernel, cudaFuncAttributeMaxDynamicSharedMemorySize, ATT_SMEM);

    const int M = M_TOK;

    // prep
    embed_kernel<<<M, 256>>>(idx, te, pe, x, xh);
    tDD_kernel<<<dim3(32, 32, 4 * L_), 256>>>(wq, wk, wv, wo, bq, bk, bv, wH, bqkv);
    tFF_kernel<<<dim3(128, 64, L_), 256>>>(w1, w2, wH);

    // grids: blockIdx.x = M-block (fastest), blockIdx.y = N-block
    const dim3 gQKV(M / 64, QKV3 / 128);         // 32 x 24  (SMALLM, 768 CTAs)
    const dim3 gW1 (M / 128, DFF_ / 128);        // 16 x 32  (WIDE, 512 CTAs)
    const dim3 gSM (M / 64, D_ / 64);            // 32 x 16  (SMALL64, 512 CTAs)
    const dim3 gLM (M / 128, (V_ + 127) / 128);  // 16 x 393 (WIDE)
    const dim3 gAT (S_ / 8, H_, B_);

    for (int l = 0; l < L_; l++) {
        const size_t lw = (size_t)l * LAYER_WELEMS;
        const __half *wqkvT = wH + lw;
        const __half *woT   = wH + lw + 3 * D_ * D_;
        const __half *w1T   = wH + lw + 4 * D_ * D_;
        const __half *w2T   = w1T + (size_t)D_ * DFF_;

        // qkv(fp16) = xh @ [Wq|Wk|Wv] + bqkv
        mma_gemm<64, 128, 32, false, false, false, true><<<gQKV, 128, SMS>>>(
            xh, wqkvT, bqkv + l * QKV3, nullptr, nullptr, qkv, M, QKV3, D_);

        attn_kernel<<<gAT, 256, ATT_SMEM>>>(qkv, y);

        // x(fp32) = x + y@Wo + bo
        mma_gemm<64, 64, 16, false, true, true, false><<<gSM, 128, SM64>>>(
            y, woT, bo + (size_t)l * D_, x, x, nullptr, M, D_, D_);

        // t(fp16) = LN(x)
        ln_kernel<<<M, 256>>>(x, ln2g + (size_t)l * D_, ln2b + (size_t)l * D_, t);

        // hb(fp16) = gelu(t@W1 + b1)
        mma_gemm<128, 128, 64, true, false, false, true><<<gW1, 128, SMW>>>(
            t, w1T, b1 + (size_t)l * DFF_, nullptr, nullptr, hb, M, DFF_, D_);

        // x(fp32) = x + hb@W2 + b2 ; xh(fp16) = x
        mma_gemm<64, 64, 16, false, true, true, true><<<gSM, 128, SM64>>>(
            hb, w2T, b2 + (size_t)l * D_, x, x, xh, M, D_, DFF_);
    }

    // final LN + weight-tied LM head
    ln_kernel<<<M, 256>>>(x, lnfg, lnfb, t);
    h2_kernel<<<(V_ * D_ / 4 + 255) / 256, 256>>>(te, teH, V_ * D_);
    mma_gemm<128, 128, 64, false, false, true, false><<<gLM, 128, SMW>>>(
        t, teH, nullptr, nullptr, out, nullptr, M, V_, D_);
}

// round 15
// speedup vs baseline: 1.8852x; 1.8418x over previous
#include <cuda_runtime.h>
#include <cuda_fp16.h>
#include <math.h>
#include <stdint.h>

// Problem constants
#define B_ 2
#define S_ 1024
#define D_ 1024
#define H_ 16
#define DK_ 64
#define DFF_ 4096
#define L_ 4
#define V_ 50257
#define M_TOK (B_ * S_)   // 2048 rows
#define QKV3 (3 * D_)     // 3072

// ---------------- scratch (static device globals; no allocation allowed) ----
__device__ float  g_x[M_TOK * D_];        // residual stream (fp32)
__device__ __half g_xh[M_TOK * D_];       // fp16 copy of x (QKV A input)
__device__ __half g_qkv[M_TOK * QKV3];    // fused q|k|v (fp16)
__device__ __half g_y[M_TOK * D_];        // attention out (fp16)
__device__ __half g_t[M_TOK * D_];        // ln out (fp16)
__device__ __half g_h[M_TOK * DFF_];      // mlp hidden (fp16)

// transposed fp16 weights: per layer [wqT][wkT][wvT][woT][w1T][w2T]
#define LAYER_WELEMS (4 * D_ * D_ + D_ * DFF_ + DFF_ * D_)
__device__ __half g_wH[(size_t)L_ * LAYER_WELEMS];
__device__ float  g_bqkv[L_ * QKV3];       // packed qkv bias (fp32)
__device__ __half g_teH[(size_t)V_ * D_];  // fp16 token embedding ([V,D]=[N,K])

// ---------------- PTX helpers (sm_80+ portable only) ----------------
__device__ __forceinline__ uint32_t smem_u32(const void* p) {
    uint32_t a;
    asm("{ .reg .u64 t; cvta.to.shared.u64 t, %1; cvt.u32.u64 %0, t; }" : "=r"(a) : "l"(p));
    return a;
}
__device__ __forceinline__ void cp_async16(uint32_t dst, const void* src, int szbytes) {
    asm volatile("cp.async.cg.shared.global [%0], [%1], 16, %2;" :: "r"(dst), "l"(src), "r"(szbytes));
}
__device__ __forceinline__ void cp_commit() { asm volatile("cp.async.commit_group;" ::: "memory"); }
template<int N> __device__ __forceinline__ void cp_wait() { asm volatile("cp.async.wait_group %0;" :: "n"(N) : "memory"); }

__device__ __forceinline__ void ldsm_x4(uint32_t& r0, uint32_t& r1, uint32_t& r2, uint32_t& r3, uint32_t addr) {
    asm volatile("ldmatrix.sync.aligned.m8n8.x4.shared.b16 {%0,%1,%2,%3}, [%4];"
                 : "=r"(r0), "=r"(r1), "=r"(r2), "=r"(r3) : "r"(addr));
}
__device__ __forceinline__ void ldsm_x4_trans(uint32_t& r0, uint32_t& r1, uint32_t& r2, uint32_t& r3, uint32_t addr) {
    asm volatile("ldmatrix.sync.aligned.m8n8.x4.trans.shared.b16 {%0,%1,%2,%3}, [%4];"
                 : "=r"(r0), "=r"(r1), "=r"(r2), "=r"(r3) : "r"(addr));
}
// fp16 MMA, fp32 accumulate
__device__ __forceinline__ void mma16816(float* c, const uint32_t* a, uint32_t b0, uint32_t b1) {
    asm volatile("mma.sync.aligned.m16n8k16.row.col.f32.f16.f16.f32 "
                 "{%0,%1,%2,%3}, {%4,%5,%6,%7}, {%8,%9}, {%0,%1,%2,%3};"
                 : "+f"(c[0]), "+f"(c[1]), "+f"(c[2]), "+f"(c[3])
                 : "r"(a[0]), "r"(a[1]), "r"(a[2]), "r"(a[3]), "r"(b0), "r"(b1));
}

#define SW128(o) ((o) ^ (((o) >> 3) & 0x70))

// ---------------- fp16 GEMM (fp32 accumulate) — R12 version ----------------
template<int BM, int BN, int WN> struct GCfg {
    static constexpr int WRN = BM / 64;
    static constexpr int WCN = BN / WN;
    static constexpr int NT  = WRN * WCN * 32;   // 128
    static constexpr int OCC = (BM == 64) ? 3 : 2;
    static constexpr int STAGE = (BM + BN) * 128;
    static constexpr int SMEM  = 3 * STAGE;
    static constexpr int NJ = WN / 8;
    static constexpr int NB = WN / 16;
};

template<int BM, int BN, int WN, bool GELU_, bool RES_, bool WF_, bool WH_>
__global__ void __launch_bounds__((GCfg<BM,BN,WN>::NT), (GCfg<BM,BN,WN>::OCC))
mma_gemm(const __half* __restrict__ A, const __half* __restrict__ Bm,
         const float* __restrict__ bias, const float* __restrict__ res,
         float* __restrict__ C, __half* __restrict__ Ch, int M, int N, int K)
{
    using CFG = GCfg<BM, BN, WN>;
    constexpr int NT = CFG::NT, STAGE = CFG::STAGE, WRN = CFG::WRN;
    constexpr int NJ = CFG::NJ, NB = CFG::NB;

    extern __shared__ __align__(1024) char smem_raw[];
    const uint32_t sb = smem_u32(smem_raw);
    const int tid = threadIdx.x, wid = tid >> 5, lane = tid & 31;
    const int bm = blockIdx.x * BM, bn = blockIdx.y * BN;
    const int wr = (WRN == 1) ? 0 : (wid & (WRN - 1));
    const int wc = (WRN == 1) ? wid : (wid >> 1);
    const int rl = lane & 15, qh = lane >> 4;

    float acc[4][NJ][4];
#pragma unroll
    for (int i = 0; i < 4; i++)
#pragma unroll
        for (int j = 0; j < NJ; j++)
#pragma unroll
            for (int r = 0; r < 4; r++) acc[i][j][r] = 0.0f;

    auto load_chunk = [&](int c, int stage) {
        const int k0 = c << 6;
        const uint32_t sA = sb + (uint32_t)stage * STAGE;
        const uint32_t sB = sA + BM * 128;
#pragma unroll
        for (int ch = tid; ch < BM * 8; ch += NT) {
            const int r = ch >> 3, qd = ch & 7;
            cp_async16(sA + SW128((uint32_t)(r * 128 + qd * 16)),
                       A + (size_t)(bm + r) * K + k0 + qd * 8, 16);
        }
#pragma unroll
        for (int ch = tid; ch < BN * 8; ch += NT) {
            const int r = ch >> 3, qd = ch & 7;
            const int gn = bn + r;
            const int vn = gn < N ? gn : N - 1;
            const int vsz = gn < N ? 16 : 0;
            cp_async16(sB + SW128((uint32_t)(r * 128 + qd * 16)),
                       Bm + (size_t)vn * K + k0 + qd * 8, vsz);
        }
    };

    const int NC = K >> 6;
    load_chunk(0, 0);
    cp_commit();
    if (NC > 1) { load_chunk(1, 1); cp_commit(); }

    int buf = 0, nxt = 2;
    for (int c = 0; c < NC; c++) {
        if (c + 1 < NC) cp_wait<1>(); else cp_wait<0>();
        __syncthreads();

        if (c + 2 < NC) { load_chunk(c + 2, nxt); cp_commit(); }

        const uint32_t tA = sb + (uint32_t)buf * STAGE;
        const uint32_t tB = tA + BM * 128;
#pragma unroll
        for (int k16 = 0; k16 < 4; k16++) {
            uint32_t a[4][4], b[NB][4];
#pragma unroll
            for (int i = 0; i < 4; i++) {
                const uint32_t off = SW128((uint32_t)((wr * 64 + i * 16 + rl) * 128 + (k16 * 2 + qh) * 16));
                ldsm_x4(a[i][0], a[i][1], a[i][2], a[i][3], tA + off);
            }
#pragma unroll
            for (int g = 0; g < NB; g++) {
                const uint32_t off = SW128((uint32_t)((wc * WN + g * 16 + rl) * 128 + (k16 * 2 + qh) * 16));
                ldsm_x4(b[g][0], b[g][1], b[g][2], b[g][3], tB + off);
            }
#pragma unroll
            for (int i = 0; i < 4; i++)
#pragma unroll
                for (int j = 0; j < NJ; j++)
                    mma16816(acc[i][j], a[i], b[j >> 1][j & 1], b[j >> 1][(j & 1) + 2]);
        }

        buf = buf == 2 ? 0 : buf + 1;
        nxt = nxt == 2 ? 0 : nxt + 1;
    }

    const int quad = lane >> 2, tq = lane & 3;
#pragma unroll
    for (int i = 0; i < 4; i++) {
        const int m0 = bm + wr * 64 + i * 16 + quad;
#pragma unroll
        for (int j = 0; j < NJ; j++) {
            const int n0 = bn + wc * WN + j * 8 + tq * 2;
#pragma unroll
            for (int half = 0; half < 2; half++) {
                const int m = m0 + half * 8;
                float c0 = acc[i][j][half * 2 + 0];
                float c1 = acc[i][j][half * 2 + 1];
                if (bias) { c0 += bias[n0]; c1 += bias[n0 + 1]; }
                if (GELU_) {
                    c0 = 0.5f * c0 * (1.0f + erff(c0 * 0.70710678118654752f));
                    c1 = 0.5f * c1 * (1.0f + erff(c1 * 0.70710678118654752f));
                }
                if (RES_) {
                    c0 += res[(size_t)m * N + n0];
                    c1 += res[(size_t)m * N + n0 + 1];
                }
                if (WF_) {
                    if (n0 < N)     C[(size_t)m * N + n0]     = c0;
                    if (n0 + 1 < N) C[(size_t)m * N + n0 + 1] = c1;
                }
                if (WH_) {
                    if (n0 < N)     Ch[(size_t)m * N + n0]     = __float2half(c0);
                    if (n0 + 1 < N) Ch[(size_t)m * N + n0 + 1] = __float2half(c1);
                }
            }
        }
    }
}

// ---------------- weight prep (transpose + fp16) ----------------
__global__ void __launch_bounds__(256) tDD_kernel(
    const float* __restrict__ wq, const float* __restrict__ wk,
    const float* __restrict__ wv, const float* __restrict__ wo,
    const float* __restrict__ bq, const float* __restrict__ bk,
    const float* __restrict__ bv, __half* __restrict__ wH, float* __restrict__ bqkv)
{
    __shared__ float tile[32][33];
    const int m = blockIdx.z, l = m >> 2, which = m & 3;
    const float* W = (which == 0 ? wq : which == 1 ? wk : which == 2 ? wv : wo)
                     + (size_t)l * D_ * D_;
    __half* WT = wH + (size_t)l * LAYER_WELEMS + (size_t)which * D_ * D_;
    const int tx = threadIdx.x & 31, ty = threadIdx.x >> 5;
    const int k0 = blockIdx.y << 5, n0 = blockIdx.x << 5;
#pragma unroll
    for (int i = 0; i < 4; i++)
        tile[ty + i * 8][tx] = W[(size_t)(k0 + ty + i * 8) * D_ + n0 + tx];
    __syncthreads();
#pragma unroll
    for (int i = 0; i < 4; i++)
        WT[(size_t)(n0 + ty + i * 8) * D_ + k0 + tx] = __float2half(tile[tx][ty + i * 8]);
    if (blockIdx.y == 0 && which < 3 && threadIdx.x < 32) {
        const float* bsrc = which == 0 ? bq : which == 1 ? bk : bv;
        bqkv[l * QKV3 + which * D_ + n0 + threadIdx.x] = bsrc[l * D_ + n0 + threadIdx.x];
    }
}

__global__ void __launch_bounds__(256) tFF_kernel(
    const float* __restrict__ w1, const float* __restrict__ w2, __half* __restrict__ wH)
{
    __shared__ float tile[32][33];
    const int l = blockIdx.z;
    const int tx = threadIdx.x & 31, ty = threadIdx.x >> 5;
    const float* W; __half* WT; int Kd, Nd, k0, n0;
    if (blockIdx.y < 32) {
        W = w1 + (size_t)l * D_ * DFF_;
        WT = wH + (size_t)l * LAYER_WELEMS + (size_t)4 * D_ * D_;
        Kd = D_; Nd = DFF_;
        k0 = blockIdx.y << 5; n0 = blockIdx.x << 5;
    } else {
        const int id = blockIdx.x + ((blockIdx.y - 32) << 7);
        W = w2 + (size_t)l * DFF_ * D_;
        WT = wH + (size_t)l * LAYER_WELEMS + (size_t)4 * D_ * D_ + (size_t)D_ * DFF_;
        Kd = DFF_; Nd = D_;
        k0 = (id >> 5) << 5; n0 = (id & 31) << 5;
    }
#pragma unroll
    for (int i = 0; i < 4; i++)
        tile[ty + i * 8][tx] = W[(size_t)(k0 + ty + i * 8) * Nd + n0 + tx];
    __syncthreads();
#pragma unroll
    for (int i = 0; i < 4; i++)
        WT[(size_t)(n0 + ty + i * 8) * Kd + k0 + tx] = __float2half(tile[tx][ty + i * 8]);
}

// elementwise fp32 -> fp16 (te -> teH); n % 4 == 0
__global__ void __launch_bounds__(256) h2_kernel(
    const float* __restrict__ x, __half* __restrict__ r, int n)
{
    const int i = (blockIdx.x * 256 + threadIdx.x) * 4;
    if (i >= n) return;
    const float4 v = *(const float4*)(x + i);
    *(__half2*)(r + i)     = __floats2half2_rn(v.x, v.y);
    *(__half2*)(r + i + 2) = __floats2half2_rn(v.z, v.w);
}

// ---------------- embedding (x fp32 + xh fp16) ----------------
__global__ void __launch_bounds__(256) embed_kernel(
    const int* __restrict__ idx, const float* __restrict__ te,
    const float* __restrict__ pe, float* __restrict__ x, __half* __restrict__ xh)
{
    const int bs = blockIdx.x;
    const int s  = bs & (S_ - 1);
    const int tok = idx[bs];
    const float4* tr = (const float4*)(te + (size_t)tok * D_);
    const float4* pr = (const float4*)(pe + (size_t)s * D_);
    float4* xo = (float4*)(x + (size_t)bs * D_);
    __half* xho = xh + (size_t)bs * D_;
    for (int i = threadIdx.x; i < D_ / 4; i += blockDim.x) {
        float4 t = tr[i], p = pr[i];
        float4 s4 = make_float4(t.x + p.x, t.y + p.y, t.z + p.z, t.w + p.w);
        xo[i] = s4;
        *(__half2*)(xho + i * 4)     = __floats2half2_rn(s4.x, s4.y);
        *(__half2*)(xho + i * 4 + 2) = __floats2half2_rn(s4.z, s4.w);
    }
}

// ---------------- layernorm (fp32 in, fp16 out) ----------------
__device__ __forceinline__ float block_reduce_sum(float val, float* sh) {
    const int lane = threadIdx.x & 31;
    const int wid  = threadIdx.x >> 5;
#pragma unroll
    for (int o = 16; o; o >>= 1) val += __shfl_down_sync(0xffffffffu, val, o);
    if (lane == 0) sh[wid] = val;
    __syncthreads();
    const int nw = (blockDim.x + 31) >> 5;
    val = (threadIdx.x < nw) ? sh[threadIdx.x] : 0.0f;
    if (wid == 0) {
#pragma unroll
        for (int o = 16; o; o >>= 1) val += __shfl_down_sync(0xffffffffu, val, o);
        if (lane == 0) sh[0] = val;
    }
    __syncthreads();
    val = sh[0];
    __syncthreads();
    return val;
}

__global__ void __launch_bounds__(256) ln_kernel(
    const float* __restrict__ x, const float* __restrict__ g,
    const float* __restrict__ bta, __half* __restrict__ out)
{
    __shared__ float red[32];
    const int row = blockIdx.x;
    const float* xr = x + (size_t)row * D_;
    float s = 0.0f, s2 = 0.0f;
    for (int i = threadIdx.x; i < D_; i += 256) {
        float v = xr[i];
        s += v; s2 += v * v;
    }
    s  = block_reduce_sum(s,  red);
    s2 = block_reduce_sum(s2, red);
    const float mean = s * (1.0f / D_);
    const float var  = s2 * (1.0f / D_) - mean * mean;
    const float rstd = rsqrtf(var + 1e-5f);
    __half* orow = out + (size_t)row * D_;
    for (int i = threadIdx.x; i < D_; i += 256)
        orow[i] = __float2half((xr[i] - mean) * rstd * g[i] + bta[i]);
}

// ---------------- MMA attention (FA2-style) ----------------
// Block: 64 queries of one (b,h); 128 threads = 4 warps; warp w -> rows w*16..+15.
// Loop over 64-key tiles: S = Q@K^T (m16n8k16, fp32 acc), causal mask + scale,
// online softmax (fp32, __expf), P repacked to fp16 A-frags IN REGISTERS,
// O += P@V with V fragments via ldmatrix.trans. Finally O /= lsum -> fp16 y.
__global__ void __launch_bounds__(128, 2) attn_kernel(
    const __half* __restrict__ qkv, __half* __restrict__ y)
{
    __shared__ __align__(1024) __half smA[3 * 64 * 64];   // Q | K | V tiles, 24 KB
    const uint32_t sbase = smem_u32(smA);
    const uint32_t Qb = sbase, Kb = sbase + 8192, Vb = sbase + 16384;

    const int tid = threadIdx.x, wid = tid >> 5, lane = tid & 31;
    const int quad = lane >> 2, tq = lane & 3;
    const int rl = lane & 15, qh = lane >> 4;
    const int s0 = blockIdx.x * 64;
    const int h = blockIdx.y, b = blockIdx.z;
    const size_t base = (size_t)b * S_ * QKV3 + (size_t)h * DK_;
    const __half* qp = qkv + base;
    const __half* kp = qkv + base + D_;
    const __half* vp = qkv + base + 2 * D_;

    // load Q tile [64 rows x 64 halves], SW128 rows of 128B
#pragma unroll
    for (int u = 0; u < 4; u++) {
        const int ch = tid + (u << 7);               // 0..511
        const int r = ch >> 3, qd = ch & 7;
        *(uint4*)((char*)smA + SW128((uint32_t)(r * 128 + qd * 16))) =
            *(const uint4*)(qp + (size_t)(s0 + r) * QKV3 + qd * 8);
    }
    __syncthreads();

    // Q A-fragments (row = wid*16 + rl), 4 k16 tiles
    uint32_t aq[4][4];
#pragma unroll
    for (int t = 0; t < 4; t++) {
        const uint32_t off = SW128((uint32_t)((wid * 16 + rl) * 128 + (t * 2 + qh) * 16));
        ldsm_x4(aq[t][0], aq[t][1], aq[t][2], aq[t][3], Qb + off);
    }

    const int r0 = s0 + wid * 16 + quad;     // rows owned by this thread
    const int r1 = r0 + 8;
    float accO[8][4];
#pragma unroll
    for (int j = 0; j < 8; j++)
#pragma unroll
        for (int r = 0; r < 4; r++) accO[j][r] = 0.0f;
    float m0 = -INFINITY, m1 = -INFINITY, l0 = 0.0f, l1 = 0.0f;

    const int ntiles = (s0 >> 6) + 1;
    for (int kt = 0; kt < ntiles; kt++) {
        const int k0 = kt << 6;
        if (kt) __syncthreads();                 // all warps done with prior K/V
        // stage K and V tiles
#pragma unroll
        for (int u = 0; u < 4; u++) {
            const int ch = tid + (u << 7);
            const int r = ch >> 3, qd = ch & 7;
            const uint32_t so = SW128((uint32_t)(r * 128 + qd * 16));
            *(uint4*)((char*)smA + 8192 + so)  = *(const uint4*)(kp + (size_t)(k0 + r) * QKV3 + qd * 8);
            *(uint4*)((char*)smA + 16384 + so) = *(const uint4*)(vp + (size_t)(k0 + r) * QKV3 + qd * 8);
        }
        __syncthreads();

        // S = Q @ K^T  (8 n-tiles of 8 keys)
        float accS[8][4];
#pragma unroll
        for (int j = 0; j < 8; j++)
#pragma unroll
            for (int r = 0; r < 4; r++) accS[j][r] = 0.0f;
#pragma unroll
        for (int t = 0; t < 4; t++) {
            uint32_t bk[4][4];
#pragma unroll
            for (int g = 0; g < 4; g++) {
                const uint32_t off = SW128((uint32_t)((g * 16 + rl) * 128 + (t * 2 + qh) * 16));
                ldsm_x4(bk[g][0], bk[g][1], bk[g][2], bk[g][3], Kb + off);
            }
#pragma unroll
            for (int j = 0; j < 8; j++)
                mma16816(accS[j], aq[t], bk[j >> 1][j & 1], bk[j >> 1][(j & 1) + 2]);
        }

        // scale + causal mask (only diagonal tile needs masking)
        const bool diag = (kt == ntiles - 1);
        float ml0 = -INFINITY, ml1 = -INFINITY;
#pragma unroll
        for (int j = 0; j < 8; j++) {
#pragma unroll
            for (int c = 0; c < 2; c++) {
                const int key = k0 + j * 8 + tq * 2 + c;
                accS[j][c]     = (!diag || key <= r0) ? accS[j][c]     * 0.125f : -INFINITY;
                accS[j][c + 2] = (!diag || key <= r1) ? accS[j][c + 2] * 0.125f : -INFINITY;
                ml0 = fmaxf(ml0, accS[j][c]);
                ml1 = fmaxf(ml1, accS[j][c + 2]);
            }
        }
        ml0 = fmaxf(ml0, __shfl_xor_sync(0xffffffffu, ml0, 1));
        ml0 = fmaxf(ml0, __shfl_xor_sync(0xffffffffu, ml0, 2));
        ml1 = fmaxf(ml1, __shfl_xor_sync(0xffffffffu, ml1, 1));
        ml1 = fmaxf(ml1, __shfl_xor_sync(0xffffffffu, ml1, 2));

        const float mn0 = fmaxf(m0, ml0), mn1 = fmaxf(m1, ml1);
        const float sc0 = __expf(m0 - mn0), sc1 = __expf(m1 - mn1);
        m0 = mn0; m1 = mn1;

        // P = exp(S - m), local sums
        float ls0 = 0.0f, ls1 = 0.0f;
#pragma unroll
        for (int j = 0; j < 8; j++) {
#pragma unroll
            for (int c = 0; c < 2; c++) {
                const float p0 = __expf(accS[j][c] - mn0);
                const float p1 = __expf(accS[j][c + 2] - mn1);
                accS[j][c] = p0; accS[j][c + 2] = p1;
                ls0 += p0; ls1 += p1;
            }
        }
        ls0 += __shfl_xor_sync(0xffffffffu, ls0, 1);
        ls0 += __shfl_xor_sync(0xffffffffu, ls0, 2);
        ls1 += __shfl_xor_sync(0xffffffffu, ls1, 1);
        ls1 += __shfl_xor_sync(0xffffffffu, ls1, 2);
        l0 = l0 * sc0 + ls0;
        l1 = l1 * sc1 + ls1;
#pragma unroll
        for (int j = 0; j < 8; j++) {
            accO[j][0] *= sc0; accO[j][1] *= sc0;
            accO[j][2] *= sc1; accO[j][3] *= sc1;
        }

        // repack P (S-accum frags) into fp16 A-fragments: k16 tile t <- n-tiles 2t, 2t+1
        uint32_t ap[4][4];
#pragma unroll
        for (int t = 0; t < 4; t++) {
            ap[t][0] = __half2_raw(__floats2half2_rn(accS[2 * t][0],     accS[2 * t][1])).x
                     | ((uint32_t)__half2_raw(__floats2half2_rn(accS[2 * t][0], accS[2 * t][1])).y << 16);
            // simpler: use unions below
        }
        // (rewritten cleanly)
#pragma unroll
        for (int t = 0; t < 4; t++) {
            __half2 h0 = __floats2half2_rn(accS[2 * t][0],     accS[2 * t][1]);
            __half2 h1 = __floats2half2_rn(accS[2 * t][2],     accS[2 * t][3]);
            __half2 h2 = __floats2half2_rn(accS[2 * t + 1][0], accS[2 * t + 1][1]);
            __half2 h3 = __floats2half2_rn(accS[2 * t + 1][2], accS[2 * t + 1][3]);
            ap[t][0] = *(uint32_t*)&h0;
            ap[t][1] = *(uint32_t*)&h1;
            ap[t][2] = *(uint32_t*)&h2;
            ap[t][3] = *(uint32_t*)&h3;
        }

        // O += P @ V  (V fragments via ldmatrix.trans: rows = keys, cols = dims)
#pragma unroll
        for (int t = 0; t < 4; t++) {
#pragma unroll
            for (int dp = 0; dp < 4; dp++) {
                uint32_t v0, v1, v2, v3;
                const uint32_t off = SW128((uint32_t)((t * 16 + rl) * 128 + dp * 32 + qh * 16));
                ldsm_x4_trans(v0, v1, v2, v3, Vb + off);
                mma16816(accO[2 * dp],     ap[t], v0, v1);
                mma16816(accO[2 * dp + 1], ap[t], v2, v3);
            }
        }
    }

    // epilogue: normalize and store fp16 y
    const float inv0 = 1.0f / l0, inv1 = 1.0f / l1;
    __half* yb = y + (size_t)b * S_ * D_ + (size_t)h * DK_;
#pragma unroll
    for (int j = 0; j < 8; j++) {
        const int col = j * 8 + tq * 2;
        *(__half2*)(yb + (size_t)r0 * D_ + col) = __floats2half2_rn(accO[j][0] * inv0, accO[j][1] * inv0);
        *(__half2*)(yb + (size_t)r1 * D_ + col) = __floats2half2_rn(accO[j][2] * inv1, accO[j][3] * inv1);
    }
}

// ---------------- driver ----------------
extern "C" void kernel_launch(void* const* d_in, const int* in_sizes, int n_in,
                              void* d_out, int out_size)
{
    const int*   idx   = (const int*)  d_in[0];
    const float* te    = (const float*)d_in[1];
    const float* pe    = (const float*)d_in[2];
    const float* wq    = (const float*)d_in[3];
    const float* bq    = (const float*)d_in[4];
    const float* wk    = (const float*)d_in[5];
    const float* bk    = (const float*)d_in[6];
    const float* wv    = (const float*)d_in[7];
    const float* bv    = (const float*)d_in[8];
    const float* wo    = (const float*)d_in[9];
    const float* bo    = (const float*)d_in[10];
    const float* ln2g  = (const float*)d_in[11];
    const float* ln2b  = (const float*)d_in[12];
    const float* w1    = (const float*)d_in[13];
    const float* b1    = (const float*)d_in[14];
    const float* w2    = (const float*)d_in[15];
    const float* b2    = (const float*)d_in[16];
    const float* lnfg  = (const float*)d_in[17];
    const float* lnfb  = (const float*)d_in[18];
    float* out = (float*)d_out;

    float *x, *bqkv;
    __half *xh, *qkv, *y, *t, *hb, *wH, *teH;
    cudaGetSymbolAddress((void**)&x,    g_x);
    cudaGetSymbolAddress((void**)&xh,   g_xh);
    cudaGetSymbolAddress((void**)&qkv,  g_qkv);
    cudaGetSymbolAddress((void**)&y,    g_y);
    cudaGetSymbolAddress((void**)&t,    g_t);
    cudaGetSymbolAddress((void**)&hb,   g_h);
    cudaGetSymbolAddress((void**)&wH,   g_wH);
    cudaGetSymbolAddress((void**)&bqkv, g_bqkv);
    cudaGetSymbolAddress((void**)&teH,  g_teH);

    constexpr int SMW = GCfg<128, 128, 64>::SMEM;   // 96 KB (WIDE)
    constexpr int SMS = GCfg<64, 128, 32>::SMEM;    // 72 KB (SMALLM)
    cudaFuncSetAttribute(mma_gemm<128, 128, 64, false, false, false, true >, cudaFuncAttributeMaxDynamicSharedMemorySize, SMW);
    cudaFuncSetAttribute(mma_gemm<128, 128, 64, true , false, false, true >, cudaFuncAttributeMaxDynamicSharedMemorySize, SMW);
    cudaFuncSetAttribute(mma_gemm<128, 128, 64, false, false, true , false>, cudaFuncAttributeMaxDynamicSharedMemorySize, SMW);
    cudaFuncSetAttribute(mma_gemm<64, 128, 32, false, true , true , false>, cudaFuncAttributeMaxDynamicSharedMemorySize, SMS);
    cudaFuncSetAttribute(mma_gemm<64, 128, 32, false, true , true , true >, cudaFuncAttributeMaxDynamicSharedMemorySize, SMS);

    const int M = M_TOK;

    // prep
    embed_kernel<<<M, 256>>>(idx, te, pe, x, xh);
    tDD_kernel<<<dim3(32, 32, 4 * L_), 256>>>(wq, wk, wv, wo, bq, bk, bv, wH, bqkv);
    tFF_kernel<<<dim3(128, 64, L_), 256>>>(w1, w2, wH);

    // grids (R12 dispatch)
    const dim3 gQKV(M / 128, QKV3 / 128);        // 16 x 24  (WIDE)
    const dim3 gW1 (M / 128, DFF_ / 128);        // 16 x 32  (WIDE)
    const dim3 gSM (M / 64, D_ / 128);           // 32 x 8   (SMALLM)
    const dim3 gLM (M / 128, (V_ + 127) / 128);  // 16 x 393 (WIDE)
    const dim3 gAT (S_ / 64, H_, B_);            // 16 x 16 x 2

    for (int l = 0; l < L_; l++) {
        const size_t lw = (size_t)l * LAYER_WELEMS;
        const __half *wqkvT = wH + lw;
        const __half *woT   = wH + lw + 3 * D_ * D_;
        const __half *w1T   = wH + lw + 4 * D_ * D_;
        const __half *w2T   = w1T + (size_t)D_ * DFF_;

        // qkv(fp16) = xh @ [Wq|Wk|Wv] + bqkv
        mma_gemm<128, 128, 64, false, false, false, true><<<gQKV, 128, SMW>>>(
            xh, wqkvT, bqkv + l * QKV3, nullptr, nullptr, qkv, M, QKV3, D_);

        attn_kernel<<<gAT, 128>>>(qkv, y);

        // x(fp32) = x + y@Wo + bo
        mma_gemm<64, 128, 32, false, true, true, false><<<gSM, 128, SMS>>>(
            y, woT, bo + (size_t)l * D_, x, x, nullptr, M, D_, D_);

        // t(fp16) = LN(x)
        ln_kernel<<<M, 256>>>(x, ln2g + (size_t)l * D_, ln2b + (size_t)l * D_, t);

        // hb(fp16) = gelu(t@W1 + b1)
        mma_gemm<128, 128, 64, true, false, false, true><<<gW1, 128, SMW>>>(
            t, w1T, b1 + (size_t)l * DFF_, nullptr, nullptr, hb, M, DFF_, D_);

        // x(fp32) = x + hb@W2 + b2 ; xh(fp16) = x
        mma_gemm<64, 128, 32, false, true, true, true><<<gSM, 128, SMS>>>(
            hb, w2T, b2 + (size_t)l * D_, x, x, xh, M, D_, DFF_);
    }

    // final LN + weight-tied LM head
    ln_kernel<<<M, 256>>>(x, lnfg, lnfb, t);
    h2_kernel<<<(V_ * D_ / 4 + 255) / 256, 256>>>(te, teH, V_ * D_);
    mma_gemm<128, 128, 64, false, false, true, false><<<gLM, 128, SMW>>>(
        t, teH, nullptr, nullptr, out, nullptr, M, V_, D_);
}